// round 12
// baseline (speedup 1.0000x reference)
#include <cuda_runtime.h>
#include <cuda_bf16.h>
#include <cstdint>

// Problem constants (fixed by the reference: B=16,S=16 -> BS=256)
#define L_TOK   128
#define NARG    8
#define NTOK    8
#define EMB_D   768
#define NP      24            // 3 arg-sets * NARG
#define BDIM    256           // 8 warps
#define NCOL    384           // columns per CTA (half of 768)
#define WSTR    132           // W smem row stride (pad: conflict-free A frags)
#define ESTR    392           // E smem row stride (pad: conflict-free B frags)
#define CHUNK_T 16            // tokens per staged chunk
#define NCHUNKS (L_TOK / CHUNK_T)   // 8
#define NT_PER_WARP 6         // 48 cols per warp / 8

struct Sm {
    float W[32 * WSTR];            // 16896 B  weight matrix (rows 25..31 = 0)
    float ebuf[2 * CHUNK_T * ESTR];// 50176 B  double-buffered E chunks
    int   s_ids[L_TOK];
    int   s_arg[NP * NTOK];
    int   s_tot[NP];
    float srow[32];                // per-row output scale (0 for rows>=25)
    float msum;
};

__device__ __forceinline__ uint32_t f2tf32(float x) {
    uint32_t r;
    asm("cvt.rna.tf32.f32 %0, %1;" : "=r"(r) : "f"(x));
    return r;
}

__global__ void __launch_bounds__(BDIM)
slmuse_gemm_kernel(const int*   __restrict__ sent_ids,
                   const int*   __restrict__ att_mask,
                   const int*   __restrict__ pred_ids,
                   const int*   __restrict__ arg0_ids,
                   const int*   __restrict__ arg1_ids,
                   const float* __restrict__ emb,
                   float*       __restrict__ out,
                   int BS)
{
    extern __shared__ char smraw[];
    Sm* sm = reinterpret_cast<Sm*>(smraw);

    const int tid   = threadIdx.x;
    const int bs    = blockIdx.x >> 1;
    const int chalf = blockIdx.x & 1;
    const int warp  = tid >> 5;
    const int lane  = tid & 31;
    const int g     = lane >> 2;       // groupID 0..7
    const int tig   = lane & 3;        // thread-in-group 0..3
    const int n0w   = warp * (NCOL / 8);   // 48-col slice base (local)

    float* out_mean = out;                               // [BS, D]
    float* out_sets = out + (size_t)BS * EMB_D;          // 3 x [BS, A, D]
    const size_t set_stride = (size_t)BS * NARG * EMB_D;

    const uint32_t eb_u32 =
        (uint32_t)__cvta_generic_to_shared(sm->ebuf);
    const float* emb_base = emb + (size_t)bs * L_TOK * EMB_D + chalf * NCOL;

    // ---- issue chunk 0 immediately (overlaps all setup below) ----
    {
        const float* src_base = emb_base;
        #pragma unroll
        for (int i = 0; i < 6; i++) {
            int idx = tid + i * BDIM;            // 0..1535
            int row = idx / 96, c4 = idx % 96;
            const float* src = src_base + row * EMB_D + c4 * 4;
            uint32_t dst = eb_u32 + (uint32_t)((row * ESTR + c4 * 4) * 4);
            asm volatile("cp.async.cg.shared.global [%0], [%1], 16;"
                         :: "r"(dst), "l"(src));
        }
        asm volatile("cp.async.commit_group;");
    }

    // ---- stage ids / arg ids, zero counters ----
    if (tid < L_TOK) sm->s_ids[tid] = sent_ids[(size_t)bs * L_TOK + tid];
    if (tid < NP * NTOK) {
        int p = tid / NTOK, t = tid % NTOK;
        int set = p / NARG, a = p % NARG;
        const int* src = (set == 0) ? pred_ids : (set == 1) ? arg0_ids : arg1_ids;
        sm->s_arg[tid] = src[((size_t)bs * NARG + a) * NTOK + t];
    }
    if (tid < NP) sm->s_tot[tid] = 0;
    if (tid == BDIM - 1) sm->msum = 0.f;
    __syncthreads();

    // ---- build W (32 x 128): row 0 = mask; rows 1..24 = match weights ----
    for (int task = tid; task < 32 * L_TOK; task += BDIM) {   // 16 iters
        int m = task >> 7;
        int l = task & (L_TOK - 1);
        float val = 0.f;
        if (m == 0) {
            val = (float)att_mask[(size_t)bs * L_TOK + l];
            atomicAdd(&sm->msum, val);
        } else if (m <= NP) {
            int p = m - 1;
            int sid = sm->s_ids[l];
            int w = 0;
            #pragma unroll
            for (int t = 0; t < NTOK; t++) {
                int aid = sm->s_arg[p * NTOK + t];
                w += (aid != 0 && aid == sid) ? 1 : 0;
            }
            val = (float)w;
            if (w) atomicAdd(&sm->s_tot[p], w);
        }
        sm->W[m * WSTR + l] = val;
    }
    __syncthreads();

    // ---- per-row output scales ----
    if (tid == 0) sm->srow[0] = 1.f / fmaxf(sm->msum, 1.f);
    else if (tid <= NP) {
        int tot = sm->s_tot[tid - 1];
        sm->srow[tid] = (tot > 0) ? (1.f / (float)tot) : 0.f;
    } else if (tid < 32) sm->srow[tid] = 0.f;
    // (ordered before epilogue by the main-loop barriers)

    // ---- main loop: 8 chunks of 16 tokens, cp.async double buffer ----
    float c_[2][NT_PER_WARP][4];
    #pragma unroll
    for (int mt = 0; mt < 2; mt++)
        #pragma unroll
        for (int nt = 0; nt < NT_PER_WARP; nt++)
            #pragma unroll
            for (int k = 0; k < 4; k++) c_[mt][nt][k] = 0.f;

    for (int c = 0; c < NCHUNKS; c++) {
        if (c + 1 < NCHUNKS) {
            const int buf = (c + 1) & 1;
            const float* src_base = emb_base + (size_t)((c + 1) * CHUNK_T) * EMB_D;
            #pragma unroll
            for (int i = 0; i < 6; i++) {
                int idx = tid + i * BDIM;
                int row = idx / 96, c4 = idx % 96;
                const float* src = src_base + row * EMB_D + c4 * 4;
                uint32_t dst = eb_u32 +
                    (uint32_t)(((buf * CHUNK_T + row) * ESTR + c4 * 4) * 4);
                asm volatile("cp.async.cg.shared.global [%0], [%1], 16;"
                             :: "r"(dst), "l"(src));
            }
            asm volatile("cp.async.commit_group;");
            asm volatile("cp.async.wait_group 1;");
        } else {
            asm volatile("cp.async.wait_group 0;");
        }
        __syncthreads();

        const float* EB = sm->ebuf + (c & 1) * CHUNK_T * ESTR;

        #pragma unroll
        for (int ks = 0; ks < 2; ks++) {
            const int K = c * CHUNK_T + ks * 8;     // global k (token) base

            // A fragments from W (values exact in tf32: small ints / 0-1)
            uint32_t a[2][4];
            #pragma unroll
            for (int mt = 0; mt < 2; mt++) {
                const float* Wr = sm->W + (mt * 16 + g) * WSTR + K;
                a[mt][0] = __float_as_uint(Wr[tig]);
                a[mt][1] = __float_as_uint(Wr[8 * WSTR + tig]);
                a[mt][2] = __float_as_uint(Wr[tig + 4]);
                a[mt][3] = __float_as_uint(Wr[8 * WSTR + tig + 4]);
            }
            // B fragments from staged E (cvt.rna to tf32)
            uint32_t b[NT_PER_WARP][2];
            #pragma unroll
            for (int nt = 0; nt < NT_PER_WARP; nt++) {
                const float* Eb = EB + (ks * 8 + tig) * ESTR + n0w + nt * 8 + g;
                b[nt][0] = f2tf32(Eb[0]);
                b[nt][1] = f2tf32(Eb[4 * ESTR]);
            }
            #pragma unroll
            for (int mt = 0; mt < 2; mt++)
                #pragma unroll
                for (int nt = 0; nt < NT_PER_WARP; nt++) {
                    asm volatile(
                        "mma.sync.aligned.m16n8k8.row.col.f32.tf32.tf32.f32 "
                        "{%0,%1,%2,%3}, {%4,%5,%6,%7}, {%8,%9}, {%0,%1,%2,%3};"
                        : "+f"(c_[mt][nt][0]), "+f"(c_[mt][nt][1]),
                          "+f"(c_[mt][nt][2]), "+f"(c_[mt][nt][3])
                        : "r"(a[mt][0]), "r"(a[mt][1]),
                          "r"(a[mt][2]), "r"(a[mt][3]),
                          "r"(b[nt][0]), "r"(b[nt][1]));
                }
        }
        __syncthreads();
    }

    // ---- epilogue: scale rows, scatter to the three output sections ----
    #pragma unroll
    for (int mt = 0; mt < 2; mt++) {
        const int r0 = mt * 16 + g;      // 0..7 or 16..23  (always valid)
        const int r1 = r0 + 8;           // 8..15 or 24..31 (valid if <=24)
        const float s0 = sm->srow[r0];
        const float s1 = sm->srow[r1 & 31];

        float* base0;
        if (r0 == 0) base0 = out_mean + (size_t)bs * EMB_D;
        else {
            int p = r0 - 1;
            base0 = out_sets + (size_t)(p >> 3) * set_stride
                  + ((size_t)bs * NARG + (p & 7)) * EMB_D;
        }
        float* base1 = nullptr;
        if (r1 <= NP) {
            int p = r1 - 1;              // r1 >= 8, never the mean row
            base1 = out_sets + (size_t)(p >> 3) * set_stride
                  + ((size_t)bs * NARG + (p & 7)) * EMB_D;
        }

        #pragma unroll
        for (int nt = 0; nt < NT_PER_WARP; nt++) {
            const int col = chalf * NCOL + n0w + nt * 8 + 2 * tig;
            float2 v0;
            v0.x = c_[mt][nt][0] * s0;
            v0.y = c_[mt][nt][1] * s0;
            *reinterpret_cast<float2*>(base0 + col) = v0;
            if (base1) {
                float2 v1;
                v1.x = c_[mt][nt][2] * s1;
                v1.y = c_[mt][nt][3] * s1;
                *reinterpret_cast<float2*>(base1 + col) = v1;
            }
        }
    }
}

extern "C" void kernel_launch(void* const* d_in, const int* in_sizes, int n_in,
                              void* d_out, int out_size)
{
    const int*   sent = (const int*)  d_in[0];
    const int*   mask = (const int*)  d_in[1];
    const int*   pred = (const int*)  d_in[2];
    const int*   a0   = (const int*)  d_in[3];
    const int*   a1   = (const int*)  d_in[4];
    const float* emb  = (const float*)d_in[5];
    float*       out  = (float*)      d_out;

    const int BS = in_sizes[0] / L_TOK;   // 256

    static int smem_set = 0;
    const int smem_bytes = (int)sizeof(Sm);
    if (!smem_set) {
        cudaFuncSetAttribute(slmuse_gemm_kernel,
                             cudaFuncAttributeMaxDynamicSharedMemorySize,
                             smem_bytes);
        smem_set = 1;
    }

    slmuse_gemm_kernel<<<BS * 2, BDIM, smem_bytes>>>(
        sent, mask, pred, a0, a1, emb, out, BS);
}